// round 15
// baseline (speedup 1.0000x reference)
#include <cuda_runtime.h>
#include <math.h>
#include <stdint.h>

#define NDA 100000
#define NQ  20000
#define EDA 1000000
#define EQ  200000
#define BB  64
#define HH  8
#define HD  128
#define HD2 256
#define NEG_SLOPE 2.0f

// ---------------- scratch ----------------
__device__ float g_ft[(size_t)NDA * HD];
__device__ float g_ftq[(size_t)NQ * HD];
__device__ float g_agg[(size_t)NDA * HD];
__device__ float g_aggq[(size_t)NQ * HD];
__device__ float g_y1[(size_t)NDA * HD2];
__device__ float g_y1q[(size_t)NQ * HD2];
__device__ float g_y2[(size_t)NDA * HD];
__device__ float g_y2q[(size_t)NQ * HD];
__device__ float g_el[NDA * HH];
__device__ float g_er[NDA * HH];
__device__ float g_s[NDA * HH];
__device__ float g_elq[NQ * HH];
__device__ float g_erq[NQ * HH];
__device__ float g_sq2[NQ * HH];
__device__ float g_eb[NQ];
__device__ int   g_deg[NDA];
__device__ int   g_coff[NDA];
__device__ int   g_cursor[NDA];
__device__ int   g_srcs[EDA];
__device__ int   g_bsum[256];
__device__ int   g_degq[NQ];
__device__ int   g_coffq[NQ];
__device__ int   g_cursorq[NQ];
__device__ int   g_srcsq[EQ];
__device__ int   g_bsumq[256];
__device__ float g_glq[BB * HD];
__device__ float g_t1[BB * HD2];
__device__ float g_t2[BB * HD2];
__device__ float g_Q[BB * HD2];
__device__ float g_gsumq[BB];
__device__ float g_accq[BB * 4];
__device__ float g_accda[BB * 4];
__device__ float g_aabq[BB * 2];
__device__ float g_aabda[BB * 2];
__device__ double g_dstat[1024];
__device__ float g_mu[512];
__device__ float g_rstd[512];
__device__ float g_pe[HH];
__device__ float g_de[HH];

__device__ __forceinline__ float eluf(float x) { return x > 0.f ? x : expm1f(x); }

__device__ __forceinline__ uint32_t smem_u32(const void* p) {
    uint32_t a;
    asm("{ .reg .u64 t; cvta.to.shared.u64 t, %1; cvt.u32.u64 %0, t; }" : "=r"(a) : "l"(p));
    return a;
}
__device__ __forceinline__ uint32_t f2tf(float x) {
    uint32_t r;
    asm("cvt.rna.tf32.f32 %0, %1;" : "=r"(r) : "f"(x));
    return r;
}
__device__ __forceinline__ void mma8(float* d, const uint32_t* a, const uint32_t* b) {
    asm volatile(
        "mma.sync.aligned.m16n8k8.row.col.f32.tf32.tf32.f32 "
        "{%0,%1,%2,%3}, {%4,%5,%6,%7}, {%8,%9}, {%0,%1,%2,%3};\n"
        : "+f"(d[0]), "+f"(d[1]), "+f"(d[2]), "+f"(d[3])
        : "r"(a[0]), "r"(a[1]), "r"(a[2]), "r"(a[3]), "r"(b[0]), "r"(b[1]));
}

#define AOFF(buf) ((buf) * 4608)
#define WOFF(buf) (9216 + (buf) * 4224)
#define A2OFF(buf) (17664 + (buf) * 4608)
#define SMEM_G0 ((9216 + 8448) * 4)
#define SMEM_G1 ((9216 + 8448 + 9216) * 4)

// 512-thread staging: 1024 16B chunks per tile, 2 per thread
__device__ __forceinline__ void stage_issue_r(uint32_t sb, int buf, const float* __restrict__ A,
                                              const float* __restrict__ A2, bool blend,
                                              const float* __restrict__ W, int rowBase,
                                              int colBase, int k0, int n, int K, int NC,
                                              int tid) {
    uint32_t abase = sb + AOFF(buf) * 4;
    uint32_t wbase = sb + WOFF(buf) * 4;
#pragma unroll
    for (int q = 0; q < 2; q++) {
        int id = tid + q * 512;
        int r = id >> 3, kq = id & 7;
        int grow = rowBase + r;
        const float* src = A + (size_t)grow * K + k0 + kq * 4;
        uint32_t dst = abase + (r * 36 + kq * 4) * 4;
        int sz = grow < n ? 16 : 0;
        asm volatile("cp.async.ca.shared.global [%0], [%1], 16, %2;" ::"r"(dst), "l"(src), "r"(sz)
                     : "memory");
    }
    if (blend) {
        uint32_t a2base = sb + A2OFF(buf) * 4;
#pragma unroll
        for (int q = 0; q < 2; q++) {
            int id = tid + q * 512;
            int r = id >> 3, kq = id & 7;
            int grow = rowBase + r;
            const float* src = A2 + (size_t)grow * K + k0 + kq * 4;
            uint32_t dst = a2base + (r * 36 + kq * 4) * 4;
            int sz = grow < n ? 16 : 0;
            asm volatile("cp.async.ca.shared.global [%0], [%1], 16, %2;" ::"r"(dst), "l"(src),
                         "r"(sz)
                         : "memory");
        }
    }
#pragma unroll
    for (int q = 0; q < 2; q++) {
        int id = tid + q * 512;
        int kk = id >> 5, nq = id & 31;
        const float* src = W + (size_t)(k0 + kk) * NC + colBase + nq * 4;
        uint32_t dst = wbase + (kk * 132 + nq * 4) * 4;
        asm volatile("cp.async.ca.shared.global [%0], [%1], 16;" ::"r"(dst), "l"(src) : "memory");
    }
    asm volatile("cp.async.commit_group;" ::: "memory");
}

// ---------------- mega W_L GEMM (512 thr, 16 warps, 32x32 warp tiles) ----------------
__global__ void __launch_bounds__(512, 2) k_gemmW(
    const float* __restrict__ hdl, const float* __restrict__ hql,
    const float* __restrict__ hd0, const float* __restrict__ hq0,
    const float* __restrict__ aabda, const float* __restrict__ aabq,
    const int* __restrict__ gid_da, const int* __restrict__ gid_q,
    const float* __restrict__ W, const float* __restrict__ bias,
    const float* __restrict__ Qb,
    float* ft, float* ftq,
    float* el, float* er, float* elq, float* erq, int YDA, int YQ) {
    extern __shared__ float smf[];
    const uint32_t sb = smem_u32(smf);
    const int tid = threadIdx.x;
    const int lane = tid & 31;
    const int wid = tid >> 5;
    const int warp_m = wid >> 2;   // 0..3
    const int warp_n = wid & 3;    // 0..3
    const int g4 = lane >> 2;
    const int t4 = lane & 3;

    int by = blockIdx.y;
    const float *A1, *A2, *acoef;
    const int* gid;
    float *C, *elo, *ero;
    int n;
    bool blend;
    if (by < YDA) {
        A1 = hdl; A2 = nullptr; acoef = nullptr; gid = gid_da; C = nullptr; elo = el; ero = er;
        n = NDA; blend = false;
    } else if (by < YDA + YQ) {
        by -= YDA;
        A1 = hql; A2 = nullptr; acoef = nullptr; gid = gid_q; C = nullptr; elo = elq; ero = erq;
        n = NQ; blend = false;
    } else if (by < 2 * YDA + YQ) {
        by -= YDA + YQ;
        A1 = hd0; A2 = hdl; acoef = aabda; gid = gid_da; C = ft; elo = nullptr; ero = nullptr;
        n = NDA; blend = true;
    } else {
        by -= 2 * YDA + YQ;
        A1 = hq0; A2 = hql; acoef = aabq; gid = gid_q; C = ftq; elo = nullptr; ero = nullptr;
        n = NQ; blend = true;
    }
    const int rowBase = by * 128;

    float c0 = 0.f, c1 = 0.f;
    if (blend) {
        int rr = rowBase + (tid >> 2);
        if (rr < n) {
            int g = gid[rr];
            c0 = acoef[2 * g];
            c1 = acoef[2 * g + 1];
        }
    }

    stage_issue_r(sb, 0, A1, A2, blend, W, rowBase, 0, 0, n, 128, 128, tid);
    stage_issue_r(sb, 1, A1, A2, blend, W, rowBase, 0, 32, n, 128, 128, tid);

    float acc[2][4][4];
#pragma unroll
    for (int mi = 0; mi < 2; mi++)
#pragma unroll
        for (int ni = 0; ni < 4; ni++)
#pragma unroll
            for (int r = 0; r < 4; r++) acc[mi][ni][r] = 0.f;

    const int nk = 4;
    for (int i = 0; i < nk; i++) {
        int p = i & 1;
        if (i + 1 < nk)
            asm volatile("cp.async.wait_group 1;" ::: "memory");
        else
            asm volatile("cp.async.wait_group 0;" ::: "memory");
        __syncthreads();
        if (blend) {
            float* a = smf + AOFF(p) + (tid >> 2) * 36 + (tid & 3) * 8;
            const float* b2 = smf + A2OFF(p) + (tid >> 2) * 36 + (tid & 3) * 8;
#pragma unroll
            for (int j = 0; j < 8; j++) a[j] = c0 * a[j] + c1 * b2[j];
            __syncthreads();
        }
        const float* Af = smf + AOFF(p);
        const float* Wf = smf + WOFF(p);
#pragma unroll
        for (int ks = 0; ks < 4; ks++) {
            int kk = ks * 8;
            uint32_t a[2][4];
#pragma unroll
            for (int mi = 0; mi < 2; mi++) {
                int r = warp_m * 32 + mi * 16 + g4;
                a[mi][0] = f2tf(Af[r * 36 + kk + t4]);
                a[mi][1] = f2tf(Af[(r + 8) * 36 + kk + t4]);
                a[mi][2] = f2tf(Af[r * 36 + kk + t4 + 4]);
                a[mi][3] = f2tf(Af[(r + 8) * 36 + kk + t4 + 4]);
            }
            uint32_t b[4][2];
#pragma unroll
            for (int ni = 0; ni < 4; ni++) {
                int c = warp_n * 32 + ni * 8 + g4;
                b[ni][0] = f2tf(Wf[(kk + t4) * 132 + c]);
                b[ni][1] = f2tf(Wf[(kk + t4 + 4) * 132 + c]);
            }
#pragma unroll
            for (int mi = 0; mi < 2; mi++)
#pragma unroll
                for (int ni = 0; ni < 4; ni++) mma8(acc[mi][ni], a[mi], b[ni]);
        }
        __syncthreads();
        if (i + 2 < nk)
            stage_issue_r(sb, p, A1, A2, blend, W, rowBase, 0, (i + 2) * 32, n, 128, 128, tid);
    }

    float* sC = smf;
#pragma unroll
    for (int mi = 0; mi < 2; mi++) {
        int lr0 = warp_m * 32 + mi * 16 + g4;
        int lr1 = lr0 + 8;
        int r0 = rowBase + lr0, r1 = rowBase + lr1;
#pragma unroll
        for (int ni = 0; ni < 4; ni++) {
            int c = warp_n * 32 + ni * 8 + t4 * 2;
            float b0 = bias[c], b1 = bias[c + 1];
            float v0 = acc[mi][ni][0] + b0, v1 = acc[mi][ni][1] + b1;
            float v2 = acc[mi][ni][2] + b0, v3 = acc[mi][ni][3] + b1;
            if (elo) {
                sC[lr0 * 132 + c] = v0;
                sC[lr0 * 132 + c + 1] = v1;
                sC[lr1 * 132 + c] = v2;
                sC[lr1 * 132 + c + 1] = v3;
            } else {
                if (r0 < n) {
                    C[(size_t)r0 * HD + c] = v0;
                    C[(size_t)r0 * HD + c + 1] = v1;
                }
                if (r1 < n) {
                    C[(size_t)r1 * HD + c] = v2;
                    C[(size_t)r1 * HD + c + 1] = v3;
                }
            }
        }
    }
    if (elo) {
        __syncthreads();
        int il = tid >> 2;             // row 0..127
        int h0 = (tid & 3) * 2;        // heads h0, h0+1
        int grow = rowBase + il;
        if (grow < n) {
            int gg = gid[grow];
            const float* f = sC + il * 132;
            float sl2[2], sr2[2];
#pragma unroll
            for (int hh = 0; hh < 2; hh++) {
                int h = h0 + hh;
                const float* q = Qb + (size_t)gg * HD2 + h * 32;
                float sl = 0.f, sr = 0.f;
#pragma unroll
                for (int c = 0; c < 16; c++) {
                    float fv = f[h * 16 + c];
                    sl = fmaf(fv, q[c], sl);
                    sr = fmaf(fv, q[16 + c], sr);
                }
                sl2[hh] = sl;
                sr2[hh] = sr;
            }
            *(float2*)(elo + (size_t)grow * HH + h0) = make_float2(sl2[0], sl2[1]);
            *(float2*)(ero + (size_t)grow * HH + h0) = make_float2(sr2[0], sr2[1]);
        }
    }
}

// ---------------- two-problem GEMM (512 thr) ----------------
template <int AMODE, int STAT>
__global__ void __launch_bounds__(512, 2) k_gemm(
    const float* __restrict__ A1a, const float* __restrict__ A1b,
    const float* __restrict__ W, const float* __restrict__ bias,
    const float* __restrict__ mu0, const float* __restrict__ rstd0,
    const float* __restrict__ mu1, const float* __restrict__ rstd1,
    float* Ca, float* Cb, double* ds0, double* ds1,
    int na, int nb, int yb, int K, int NC) {
    extern __shared__ float smf[];
    __shared__ float sstat[256];
    const uint32_t sb = smem_u32(smf);
    const int tid = threadIdx.x;
    const int lane = tid & 31;
    const int wid = tid >> 5;
    const int warp_m = wid >> 2;
    const int warp_n = wid & 3;
    const int g4 = lane >> 2;
    const int t4 = lane & 3;

    int by = blockIdx.y;
    const float *A1, *mu, *rstd;
    float* C;
    double* dstat;
    int n;
    if (by < yb) {
        A1 = A1a; C = Ca; dstat = ds0; n = na; mu = mu0; rstd = rstd0;
    } else {
        by -= yb;
        A1 = A1b; C = Cb; dstat = ds1; n = nb; mu = mu1; rstd = rstd1;
    }
    const int rowBase = by * 128;
    const int colBase = blockIdx.x * 128;

    if (STAT && tid < 256) sstat[tid] = 0.f;

    stage_issue_r(sb, 0, A1, nullptr, false, W, rowBase, colBase, 0, n, K, NC, tid);
    stage_issue_r(sb, 1, A1, nullptr, false, W, rowBase, colBase, 32, n, K, NC, tid);

    float acc[2][4][4];
#pragma unroll
    for (int mi = 0; mi < 2; mi++)
#pragma unroll
        for (int ni = 0; ni < 4; ni++)
#pragma unroll
            for (int r = 0; r < 4; r++) acc[mi][ni][r] = 0.f;

    const int nk = K >> 5;
    for (int i = 0; i < nk; i++) {
        int p = i & 1;
        if (i + 1 < nk)
            asm volatile("cp.async.wait_group 1;" ::: "memory");
        else
            asm volatile("cp.async.wait_group 0;" ::: "memory");
        __syncthreads();
        if (AMODE == 2) {
            int kg = i * 32 + (tid & 3) * 8;
            float* a = smf + AOFF(p) + (tid >> 2) * 36 + (tid & 3) * 8;
#pragma unroll
            for (int j = 0; j < 8; j++) a[j] = eluf((a[j] - mu[kg + j]) * rstd[kg + j]);
            __syncthreads();
        }
        const float* Af = smf + AOFF(p);
        const float* Wf = smf + WOFF(p);
#pragma unroll
        for (int ks = 0; ks < 4; ks++) {
            int kk = ks * 8;
            uint32_t a[2][4];
#pragma unroll
            for (int mi = 0; mi < 2; mi++) {
                int r = warp_m * 32 + mi * 16 + g4;
                a[mi][0] = f2tf(Af[r * 36 + kk + t4]);
                a[mi][1] = f2tf(Af[(r + 8) * 36 + kk + t4]);
                a[mi][2] = f2tf(Af[r * 36 + kk + t4 + 4]);
                a[mi][3] = f2tf(Af[(r + 8) * 36 + kk + t4 + 4]);
            }
            uint32_t b[4][2];
#pragma unroll
            for (int ni = 0; ni < 4; ni++) {
                int c = warp_n * 32 + ni * 8 + g4;
                b[ni][0] = f2tf(Wf[(kk + t4) * 132 + c]);
                b[ni][1] = f2tf(Wf[(kk + t4 + 4) * 132 + c]);
            }
#pragma unroll
            for (int mi = 0; mi < 2; mi++)
#pragma unroll
                for (int ni = 0; ni < 4; ni++) mma8(acc[mi][ni], a[mi], b[ni]);
        }
        __syncthreads();
        if (i + 2 < nk)
            stage_issue_r(sb, p, A1, nullptr, false, W, rowBase, colBase, (i + 2) * 32, n, K, NC,
                          tid);
    }

    float cs[8], cq[8];
#pragma unroll
    for (int i = 0; i < 8; i++) { cs[i] = 0.f; cq[i] = 0.f; }

#pragma unroll
    for (int mi = 0; mi < 2; mi++) {
        int r0 = rowBase + warp_m * 32 + mi * 16 + g4;
        int r1 = r0 + 8;
#pragma unroll
        for (int ni = 0; ni < 4; ni++) {
            int c = colBase + warp_n * 32 + ni * 8 + t4 * 2;
            float b0 = bias[c], b1 = bias[c + 1];
            if (r0 < n) {
                float v0 = acc[mi][ni][0] + b0, v1 = acc[mi][ni][1] + b1;
                C[(size_t)r0 * NC + c] = v0;
                C[(size_t)r0 * NC + c + 1] = v1;
                if (STAT) {
                    cs[ni * 2] += v0; cq[ni * 2] += v0 * v0;
                    cs[ni * 2 + 1] += v1; cq[ni * 2 + 1] += v1 * v1;
                }
            }
            if (r1 < n) {
                float v2 = acc[mi][ni][2] + b0, v3 = acc[mi][ni][3] + b1;
                C[(size_t)r1 * NC + c] = v2;
                C[(size_t)r1 * NC + c + 1] = v3;
                if (STAT) {
                    cs[ni * 2] += v2; cq[ni * 2] += v2 * v2;
                    cs[ni * 2 + 1] += v3; cq[ni * 2 + 1] += v3 * v3;
                }
            }
        }
    }
    if (STAT) {
#pragma unroll
        for (int i = 0; i < 8; i++) {
            float s = cs[i], q = cq[i];
            s += __shfl_down_sync(0xffffffffu, s, 16);
            q += __shfl_down_sync(0xffffffffu, q, 16);
            s += __shfl_down_sync(0xffffffffu, s, 8);
            q += __shfl_down_sync(0xffffffffu, q, 8);
            s += __shfl_down_sync(0xffffffffu, s, 4);
            q += __shfl_down_sync(0xffffffffu, q, 4);
            if (g4 == 0) {
                int c = warp_n * 32 + (i >> 1) * 8 + t4 * 2 + (i & 1);
                atomicAdd(&sstat[c], s);
                atomicAdd(&sstat[128 + c], q);
            }
        }
        __syncthreads();
        if (tid < 128) {
            atomicAdd(&dstat[colBase + tid], (double)sstat[tid]);
            atomicAdd(&dstat[256 + colBase + tid], (double)sstat[128 + tid]);
        }
    }
}

// ---------------- fills ----------------
__global__ void k_zero0(float* glq, float* gsumq, float* accq, float* accda, float* pe, float* de,
                        int* dga, int* dgb, double* dstat) {
    int i = blockIdx.x * blockDim.x + threadIdx.x;
    if (i < NDA) dga[i] = 0;
    if (i < NQ) dgb[i] = 0;
    if (i < BB * HD) glq[i] = 0.f;
    if (i < BB) gsumq[i] = 0.f;
    if (i < BB * 4) { accq[i] = 0.f; accda[i] = 0.f; }
    if (i < HH) { pe[i] = 0.f; de[i] = 0.f; }
    if (i < 1024) dstat[i] = 0.0;
}

// ---------------- gate kernels ----------------
__global__ void k_gap_pool(const float* __restrict__ M, const int* __restrict__ gid,
                           const float* __restrict__ e, const float* __restrict__ gsum,
                           float* pool, int n) {
    int w = (blockIdx.x * blockDim.x + threadIdx.x) >> 5;
    int lane = threadIdx.x & 31;
    if (w >= n) return;
    int b = gid[w];
    float wt = e[w] / gsum[b];
    const float* row = M + (size_t)w * HD;
#pragma unroll
    for (int j = lane; j < HD; j += 32) atomicAdd(&pool[b * HD + j], wt * row[j]);
}

__global__ void __launch_bounds__(1024) k_gapdots_b(
    const float* __restrict__ h0a, const float* __restrict__ hla, const int* __restrict__ gia,
    float* acca,
    const float* __restrict__ h0b, const float* __restrict__ hlb, const int* __restrict__ gib,
    float* accb,
    const float* __restrict__ w1, const float* __restrict__ b1, const float* __restrict__ w2,
    const float* __restrict__ b2, const float* __restrict__ qc,
    const float* __restrict__ wq, const float* __restrict__ bq, float* ebuf, float* gsumq,
    int ybreak) {
    __shared__ int sgid[32];
    __shared__ float sv[32][5];
    const float *M1, *M2;
    const int* gid;
    float* acc;
    int nodeBase;
    bool isq = (int)blockIdx.x >= ybreak;
    if (!isq) {
        M1 = h0a; M2 = hla; gid = gia; acc = acca; nodeBase = blockIdx.x * 32;
    } else {
        M1 = h0b; M2 = hlb; gid = gib; acc = accb; nodeBase = (blockIdx.x - ybreak) * 32;
    }
    int wid = threadIdx.x >> 5, lane = threadIdx.x & 31;
    int node = nodeBase + wid;
    {
        float4 a = ((const float4*)(M1 + (size_t)node * HD))[lane];
        float4 bb = ((const float4*)(M2 + (size_t)node * HD))[lane];
        float4 w1v = ((const float4*)w1)[lane];
        float4 w2v = ((const float4*)w2)[lane];
        float4 qv = ((const float4*)qc)[lane];
        float s1 = a.x * w1v.x + a.y * w1v.y + a.z * w1v.z + a.w * w1v.w;
        float q1 = a.x * qv.x + a.y * qv.y + a.z * qv.z + a.w * qv.w;
        float s2 = bb.x * w2v.x + bb.y * w2v.y + bb.z * w2v.z + bb.w * w2v.w;
        float q2 = bb.x * qv.x + bb.y * qv.y + bb.z * qv.z + bb.w * qv.w;
        float s3 = 0.f;
        if (isq) {
            float4 wqv = ((const float4*)wq)[lane];
            s3 = bb.x * wqv.x + bb.y * wqv.y + bb.z * wqv.z + bb.w * wqv.w;
        }
#pragma unroll
        for (int o = 16; o; o >>= 1) {
            s1 += __shfl_down_sync(0xffffffffu, s1, o);
            q1 += __shfl_down_sync(0xffffffffu, q1, o);
            s2 += __shfl_down_sync(0xffffffffu, s2, o);
            q2 += __shfl_down_sync(0xffffffffu, q2, o);
            s3 += __shfl_down_sync(0xffffffffu, s3, o);
        }
        if (lane == 0) {
            float e1 = expf(s1 + b1[0]), e2 = expf(s2 + b2[0]);
            sgid[wid] = gid[node];
            sv[wid][0] = e1; sv[wid][1] = e1 * q1; sv[wid][2] = e2; sv[wid][3] = e2 * q2;
            if (isq) {
                float e3 = expf(s3 + bq[0]);
                ebuf[node] = e3;
                sv[wid][4] = e3;
            }
        }
    }
    __syncthreads();
    int ncomp = isq ? 5 : 4;
    if ((int)threadIdx.x < ncomp) {
        int comp = threadIdx.x;
        int cur = -2;
        float a = 0.f;
        for (int i = 0; i < 32; i++) {
            int g = sgid[i];
            if (g != cur) {
                if (cur >= 0) {
                    if (comp < 4) atomicAdd(&acc[cur * 4 + comp], a);
                    else atomicAdd(&gsumq[cur], a);
                }
                cur = g;
                a = 0.f;
            }
            a += sv[i][comp];
        }
        if (cur >= 0) {
            if (comp < 4) atomicAdd(&acc[cur * 4 + comp], a);
            else atomicAdd(&gsumq[cur], a);
        }
    }
}

// ---------------- CSR build (vectorized) ----------------
__global__ void k_hist_b(const int4* __restrict__ dsta, int* dga, const int4* __restrict__ dstb,
                         int* dgb, int E4a, int E4b) {
    int t = blockIdx.x * blockDim.x + threadIdx.x;
    if (t < E4a) {
        int4 d = __ldg(&dsta[t]);
        atomicAdd(&dga[d.x], 1);
        atomicAdd(&dga[d.y], 1);
        atomicAdd(&dga[d.z], 1);
        atomicAdd(&dga[d.w], 1);
    } else {
        t -= E4a;
        if (t < E4b) {
            int4 d = __ldg(&dstb[t]);
            atomicAdd(&dgb[d.x], 1);
            atomicAdd(&dgb[d.y], 1);
            atomicAdd(&dgb[d.z], 1);
            atomicAdd(&dgb[d.w], 1);
        }
    }
}
__global__ void k_scan1_b(const int* __restrict__ dga, int* coffa, int* bsuma,
                          const int* __restrict__ dgb, int* coffb, int* bsumb, int na, int nb,
                          int nba) {
    __shared__ int sh[512];
    const int* dg;
    int *outp, *bsum;
    int n, bid;
    if ((int)blockIdx.x < nba) { dg = dga; outp = coffa; bsum = bsuma; n = na; bid = blockIdx.x; }
    else { dg = dgb; outp = coffb; bsum = bsumb; n = nb; bid = blockIdx.x - nba; }
    int base = bid * 512, t = threadIdx.x;
    int v0 = (base + t < n) ? dg[base + t] : 0;
    int v1 = (base + 256 + t < n) ? dg[base + 256 + t] : 0;
    sh[t] = v0; sh[t + 256] = v1;
    __syncthreads();
    for (int off = 1; off < 512; off <<= 1) {
        int i0 = t, i1 = t + 256;
        int n0 = sh[i0] + ((i0 >= off) ? sh[i0 - off] : 0);
        int n1 = sh[i1] + ((i1 >= off) ? sh[i1 - off] : 0);
        __syncthreads();
        sh[i0] = n0; sh[i1] = n1;
        __syncthreads();
    }
    if (base + t < n) outp[base + t] = sh[t] - v0;
    if (base + 256 + t < n) outp[base + 256 + t] = sh[t + 256] - v1;
    if (t == 0) bsum[bid] = sh[511];
}
__global__ void k_scan2_comb(int* bsuma, int nba, int* bsumb, int nbb,
                             const float* __restrict__ accq, float* aabq,
                             const float* __restrict__ accda, float* aabda) {
    __shared__ int sh[256];
    if (blockIdx.x < 2) {
        int* bsum = blockIdx.x == 0 ? bsuma : bsumb;
        int nb = blockIdx.x == 0 ? nba : nbb;
        int t = threadIdx.x;
        int v = (t < nb) ? bsum[t] : 0;
        sh[t] = v;
        __syncthreads();
        for (int off = 1; off < 256; off <<= 1) {
            int x = sh[t] + ((t >= off) ? sh[t - off] : 0);
            __syncthreads();
            sh[t] = x;
            __syncthreads();
        }
        if (t < nb) bsum[t] = sh[t] - v;
        return;
    }
    int t = threadIdx.x;
    if (t < 128) {
        const float* acc = t < BB ? accq : accda;
        float* aab = t < BB ? aabq : aabda;
        int b = t & (BB - 1);
        float d1 = acc[b * 4 + 1] / acc[b * 4 + 0];
        float d2 = acc[b * 4 + 3] / acc[b * 4 + 2];
        float mm = fmaxf(d1, d2);
        float e1 = expf(d1 - mm), e2 = expf(d2 - mm);
        float ss = e1 + e2;
        aab[2 * b] = e1 / ss;
        aab[2 * b + 1] = e2 / ss;
    }
}
__global__ void k_scan3_b(int* coffa, int* cura, const int* __restrict__ bsuma, int* coffb,
                          int* curb, const int* __restrict__ bsumb, int na, int nb) {
    int i = blockIdx.x * blockDim.x + threadIdx.x;
    if (i < na) {
        int v = coffa[i] + bsuma[i >> 9];
        coffa[i] = v;
        cura[i] = v;
    } else {
        i -= na;
        if (i < nb) {
            int v = coffb[i] + bsumb[i >> 9];
            coffb[i] = v;
            curb[i] = v;
        }
    }
}
__global__ void k_scatter_b(const int4* __restrict__ srca, const int4* __restrict__ dsta,
                            int* cura, int* srcsa, const int4* __restrict__ srcb,
                            const int4* __restrict__ dstb, int* curb, int* srcsb, int E4a,
                            int E4b) {
    int t = blockIdx.x * blockDim.x + threadIdx.x;
    if (t < E4a) {
        int4 d = __ldg(&dsta[t]);
        int4 s = __ldg(&srca[t]);
        srcsa[atomicAdd(&cura[d.x], 1)] = s.x;
        srcsa[atomicAdd(&cura[d.y], 1)] = s.y;
        srcsa[atomicAdd(&cura[d.z], 1)] = s.z;
        srcsa[atomicAdd(&cura[d.w], 1)] = s.w;
    } else {
        t -= E4a;
        if (t < E4b) {
            int4 d = __ldg(&dstb[t]);
            int4 s = __ldg(&srcb[t]);
            srcsb[atomicAdd(&curb[d.x], 1)] = s.x;
            srcsb[atomicAdd(&curb[d.y], 1)] = s.y;
            srcsb[atomicAdd(&curb[d.z], 1)] = s.z;
            srcsb[atomicAdd(&curb[d.w], 1)] = s.w;
        }
    }
}

// ---------------- batched single-pass edge softmax + aggregation ----------------
__global__ void k_node_agg_b(const int* __restrict__ srcsa, const int* __restrict__ coffa,
                             const int* __restrict__ dga, const float* __restrict__ ela,
                             const float* __restrict__ era, const float* __restrict__ fta,
                             float* agga, float* sa, const int* __restrict__ srcsb,
                             const int* __restrict__ coffb, const int* __restrict__ dgb,
                             const float* __restrict__ elb, const float* __restrict__ erb,
                             const float* __restrict__ ftb, float* aggb, float* sb2, int na,
                             int nb) {
    int w = (blockIdx.x * blockDim.x + threadIdx.x) >> 5;
    int lane = threadIdx.x & 31;
    const int *srcs, *coff, *dg;
    const float *el, *er, *ft;
    float *agg, *s;
    if (w < na) {
        srcs = srcsa; coff = coffa; dg = dga; el = ela; er = era; ft = fta; agg = agga; s = sa;
    } else {
        w -= na;
        if (w >= nb) return;
        srcs = srcsb; coff = coffb; dg = dgb; el = elb; er = erb; ft = ftb; agg = aggb; s = sb2;
    }
    int h = lane >> 2;
    int off = coff[w], d = dg[w];
    float erv = er[w * HH + h];
    float wsum = 0.f;
    float4 acc = make_float4(0.f, 0.f, 0.f, 0.f);
    int sn_next = (d > 0) ? __ldg(&srcs[off]) : 0;
#pragma unroll 4
    for (int j = 0; j < d; j++) {
        int sn = sn_next;
        if (j + 1 < d) sn_next = __ldg(&srcs[off + j + 1]);
        float elv = __ldg(&el[sn * HH + h]);
        float4 fv = __ldg((const float4*)(ft + (size_t)sn * HD + lane * 4));
        float v = elv + erv;
        v = v > 0.f ? v : NEG_SLOPE * v;
        float wt = expf(v);
        wsum += wt;
        acc.x = fmaf(wt, fv.x, acc.x);
        acc.y = fmaf(wt, fv.y, acc.y);
        acc.z = fmaf(wt, fv.z, acc.z);
        acc.w = fmaf(wt, fv.w, acc.w);
    }
    float inv = wsum > 0.f ? 1.f / wsum : 0.f;
    acc.x *= inv; acc.y *= inv; acc.z *= inv; acc.w *= inv;
    *(float4*)(agg + (size_t)w * HD + lane * 4) = acc;
    if ((lane & 3) == 0) s[w * HH + h] = wsum;
}

// ---------------- bn finalize (self-zeroing) / apply ----------------
__global__ void k_bnfin2(double* st0, int n0, float* mu0, float* rstd0, double* st1, int n1,
                         float* mu1, float* rstd1, int C) {
    int t = threadIdx.x;
    double* st;
    float *mu, *rstd;
    int n, c;
    if (t < C) { st = st0; mu = mu0; rstd = rstd0; n = n0; c = t; }
    else { st = st1; mu = mu1; rstd = rstd1; n = n1; c = t - C; }
    double m = st[c] / n;
    double v = st[256 + c] / n - m * m;
    if (v < 0.0) v = 0.0;
    mu[c] = (float)m;
    rstd[c] = (float)(1.0 / sqrt(v + 1e-5));
    st[c] = 0.0;
    st[256 + c] = 0.0;
}
__global__ void k_bnelu(const float* __restrict__ Y, const float* __restrict__ mu,
                        const float* __restrict__ rstd, float* outp, long long total, int C) {
    long long i = (long long)blockIdx.x * blockDim.x + threadIdx.x;
    if (i < total) {
        int c = (int)(i % C);
        outp[i] = eluf((Y[i] - mu[c]) * rstd[c]);
    }
}
__global__ void k_final_b(const float* __restrict__ hla, const float* __restrict__ y2a,
                          const float* __restrict__ mu0, const float* __restrict__ rstd0,
                          float* outa, const float* __restrict__ hlb,
                          const float* __restrict__ y2b, const float* __restrict__ mu1,
                          const float* __restrict__ rstd1, float* outb, long long ta,
                          long long tb) {
    long long i = (long long)blockIdx.x * blockDim.x + threadIdx.x;
    const float *hl, *Y, *mu, *rstd;
    float* outp;
    if (i < ta) { hl = hla; Y = y2a; mu = mu0; rstd = rstd0; outp = outa; }
    else {
        i -= ta;
        if (i >= tb) return;
        hl = hlb; Y = y2b; mu = mu1; rstd = rstd1; outp = outb;
    }
    int c = (int)(i & (HD - 1));
    outp[i] = hl[i] + eluf((Y[i] - mu[c]) * rstd[c]);
}

// ---------------- loss ----------------
__global__ void k_pesum_b(const int* __restrict__ peid, int npe, float* peout,
                          const int* __restrict__ deid, int nde, float* deout,
                          const int* __restrict__ src, const int* __restrict__ dst,
                          const float* __restrict__ el, const float* __restrict__ er,
                          const float* __restrict__ s) {
    const int* ids;
    float* out8;
    int nids, bid;
    int half = gridDim.x / 2;
    if ((int)blockIdx.x < half) { ids = peid; out8 = peout; nids = npe; bid = blockIdx.x; }
    else { ids = deid; out8 = deout; nids = nde; bid = blockIdx.x - half; }
    float acc[HH];
#pragma unroll
    for (int h = 0; h < HH; h++) acc[h] = 0.f;
    for (int i = bid * blockDim.x + threadIdx.x; i < nids; i += half * blockDim.x) {
        int e = ids[i];
        int se = src[e] * HH, de = dst[e] * HH;
#pragma unroll
        for (int h = 0; h < HH; h++) {
            float v = el[se + h] + er[de + h];
            v = v > 0.f ? v : NEG_SLOPE * v;
            acc[h] += expf(v) / s[de + h];
        }
    }
#pragma unroll
    for (int h = 0; h < HH; h++)
#pragma unroll
        for (int o = 16; o; o >>= 1) acc[h] += __shfl_down_sync(0xffffffffu, acc[h], o);
    if ((threadIdx.x & 31) == 0)
#pragma unroll
        for (int h = 0; h < HH; h++) atomicAdd(&out8[h], acc[h]);
}
__global__ void k_loss(const float* pe, const float* de, const int* lenp, float* outp) {
    float sum = 0.f;
#pragma unroll
    for (int h = 0; h < HH; h++) sum += pe[h] - de[h];
    outp[0] = -sum / (8.0f * (float)lenp[0]);
}

// ---------------- host ----------------
static inline int cdiv(long long a, long long b) { return (int)((a + b - 1) / b); }

extern "C" void kernel_launch(void* const* d_in, const int* in_sizes, int n_in, void* d_out,
                              int out_size) {
    const float* h_da_last = (const float*)d_in[0];
    const float* h_q_last  = (const float*)d_in[1];
    const float* h_da_0    = (const float*)d_in[2];
    const float* h_q_0     = (const float*)d_in[3];
    const float* W_L       = (const float*)d_in[4];
    const float* b_L       = (const float*)d_in[5];
    const float* gateq_W   = (const float*)d_in[6];
    const float* gateq_b   = (const float*)d_in[7];
    const float* gate1_W   = (const float*)d_in[8];
    const float* gate1_b   = (const float*)d_in[9];
    const float* gate2_W   = (const float*)d_in[10];
    const float* gate2_b   = (const float*)d_in[11];
    const float* Q_comb    = (const float*)d_in[12];
    const float* Qf_W1     = (const float*)d_in[13];
    const float* Qf_b1     = (const float*)d_in[14];
    const float* Qf_W2     = (const float*)d_in[15];
    const float* Qf_b2     = (const float*)d_in[16];
    const float* end_W1    = (const float*)d_in[17];
    const float* end_b1    = (const float*)d_in[18];
    const float* end_W2    = (const float*)d_in[19];
    const float* end_b2    = (const float*)d_in[20];
    const int* src_da = (const int*)d_in[21];
    const int* dst_da = (const int*)d_in[22];
    const int* src_q  = (const int*)d_in[23];
    const int* dst_q  = (const int*)d_in[24];
    const int* gid_da = (const int*)d_in[25];
    const int* gid_q  = (const int*)d_in[26];
    const int* PEid   = (const int*)d_in[27];
    const int* DEid   = (const int*)d_in[28];
    const int* lenp   = (const int*)d_in[29];
    int nPE = in_sizes[27], nDE = in_sizes[28];

    float* outp = (float*)d_out;
    float* out_da = outp;
    float* out_q = outp + (long long)NDA * HD;
    float* out_loss = outp + (long long)NDA * HD + (long long)NQ * HD;

    float *ft, *ftq, *agg, *aggq, *y1, *y1q, *y2, *y2q;
    float *el, *er, *ss, *elq, *erq, *sq2, *eb;
    float *glq, *t1, *t2, *Qb, *gsumq, *accq, *accda, *aabq, *aabda, *mu, *rstd, *pe, *de;
    double* dstat;
    int *dg, *coff, *cursor, *srcs, *bsum, *dgq, *coffq, *cursorq, *srcsq, *bsumq;
    cudaGetSymbolAddress((void**)&ft, g_ft);
    cudaGetSymbolAddress((void**)&ftq, g_ftq);
    cudaGetSymbolAddress((void**)&agg, g_agg);
    cudaGetSymbolAddress((void**)&aggq, g_aggq);
    cudaGetSymbolAddress((void**)&y1, g_y1);
    cudaGetSymbolAddress((void**)&y1q, g_y1q);
    cudaGetSymbolAddress((void**)&y2, g_y2);
    cudaGetSymbolAddress((void**)&y2q, g_y2q);
    cudaGetSymbolAddress((void**)&el, g_el);
    cudaGetSymbolAddress((void**)&er, g_er);
    cudaGetSymbolAddress((void**)&ss, g_s);
    cudaGetSymbolAddress((void**)&elq, g_elq);
    cudaGetSymbolAddress((void**)&erq, g_erq);
    cudaGetSymbolAddress((void**)&sq2, g_sq2);
    cudaGetSymbolAddress((void**)&eb, g_eb);
    cudaGetSymbolAddress((void**)&glq, g_glq);
    cudaGetSymbolAddress((void**)&t1, g_t1);
    cudaGetSymbolAddress((void**)&t2, g_t2);
    cudaGetSymbolAddress((void**)&Qb, g_Q);
    cudaGetSymbolAddress((void**)&gsumq, g_gsumq);
    cudaGetSymbolAddress((void**)&accq, g_accq);
    cudaGetSymbolAddress((void**)&accda, g_accda);
    cudaGetSymbolAddress((void**)&aabq, g_aabq);
    cudaGetSymbolAddress((void**)&aabda, g_aabda);
    cudaGetSymbolAddress((void**)&mu, g_mu);
    cudaGetSymbolAddress((void**)&rstd, g_rstd);
    cudaGetSymbolAddress((void**)&pe, g_pe);
    cudaGetSymbolAddress((void**)&de, g_de);
    cudaGetSymbolAddress((void**)&dstat, g_dstat);
    cudaGetSymbolAddress((void**)&dg, g_deg);
    cudaGetSymbolAddress((void**)&coff, g_coff);
    cudaGetSymbolAddress((void**)&cursor, g_cursor);
    cudaGetSymbolAddress((void**)&srcs, g_srcs);
    cudaGetSymbolAddress((void**)&bsum, g_bsum);
    cudaGetSymbolAddress((void**)&dgq, g_degq);
    cudaGetSymbolAddress((void**)&coffq, g_coffq);
    cudaGetSymbolAddress((void**)&cursorq, g_cursorq);
    cudaGetSymbolAddress((void**)&srcsq, g_srcsq);
    cudaGetSymbolAddress((void**)&bsumq, g_bsumq);

    double* dstat1 = dstat + 512;
    float* mu1 = mu + 256;
    float* rstd1 = rstd + 256;

    cudaFuncSetAttribute(k_gemmW, cudaFuncAttributeMaxDynamicSharedMemorySize, SMEM_G1);
    cudaFuncSetAttribute(k_gemm<0, 1>, cudaFuncAttributeMaxDynamicSharedMemorySize, SMEM_G0);
    cudaFuncSetAttribute(k_gemm<2, 1>, cudaFuncAttributeMaxDynamicSharedMemorySize, SMEM_G0);

    const int YDA = cdiv(NDA, 128), YQ = cdiv(NQ, 128);
    const int E4A = EDA / 4, E4B = EQ / 4;

    // prep
    k_zero0<<<cdiv(NDA, 256), 256>>>(glq, gsumq, accq, accda, pe, de, dg, dgq, dstat);
    k_gapdots_b<<<NDA / 32 + NQ / 32, 1024>>>(h_da_0, h_da_last, gid_da, accda, h_q_0, h_q_last,
                                              gid_q, accq, gate1_W, gate1_b, gate2_W, gate2_b,
                                              Q_comb, gateq_W, gateq_b, eb, gsumq, NDA / 32);
    k_gap_pool<<<cdiv((long long)NQ * 32, 256), 256>>>(h_q_last, gid_q, eb, gsumq, glq, NQ);
    k_hist_b<<<cdiv(E4A + E4B, 256), 256>>>((const int4*)dst_da, dg, (const int4*)dst_q, dgq, E4A,
                                            E4B);
    // Qf FNN -> Qb
    k_gemm<0, 1><<<dim3(2, 1), 512, SMEM_G0>>>(glq, nullptr, Qf_W1, Qf_b1, nullptr, nullptr,
                                               nullptr, nullptr, t1, nullptr, dstat, nullptr, BB,
                                               0, 1, 128, 256);
    k_bnfin2<<<1, 512>>>(dstat, BB, mu, rstd, dstat1, 1, mu1, rstd1, 256);
    k_gemm<2, 1><<<dim3(2, 1), 512, SMEM_G0>>>(t1, nullptr, Qf_W2, Qf_b2, mu, rstd, nullptr,
                                               nullptr, t2, nullptr, dstat, nullptr, BB, 0, 1,
                                               256, 256);
    k_bnfin2<<<1, 512>>>(dstat, BB, mu, rstd, dstat1, 1, mu1, rstd1, 256);
    k_bnelu<<<cdiv(BB * 256, 256), 256>>>(t2, mu, rstd, Qb, (long long)BB * 256, 256);
    // CSR
    int NBA = cdiv(NDA, 512), NBB = cdiv(NQ, 512);
    k_scan1_b<<<NBA + NBB, 256>>>(dg, coff, bsum, dgq, coffq, bsumq, NDA, NQ, NBA);
    k_scan2_comb<<<3, 256>>>(bsum, NBA, bsumq, NBB, accq, aabq, accda, aabda);
    k_scan3_b<<<cdiv(NDA + NQ, 256), 256>>>(coff, cursor, bsum, coffq, cursorq, bsumq, NDA, NQ);
    k_scatter_b<<<cdiv(E4A + E4B, 256), 256>>>((const int4*)src_da, (const int4*)dst_da, cursor,
                                               srcs, (const int4*)src_q, (const int4*)dst_q,
                                               cursorq, srcsq, E4A, E4B);

    // mega W_L GEMM (el/er fused; no feat stores)
    k_gemmW<<<dim3(1, 2 * (YDA + YQ)), 512, SMEM_G1>>>(
        h_da_last, h_q_last, h_da_0, h_q_0, aabda, aabq, gid_da, gid_q, W_L, b_L, Qb, ft, ftq, el,
        er, elq, erq, YDA, YQ);

    // batched node agg
    k_node_agg_b<<<cdiv((long long)(NDA + NQ) * 32, 256), 256>>>(
        srcs, coff, dg, el, er, ft, agg, ss, srcsq, coffq, dgq, elq, erq, ftq, aggq, sq2, NDA, NQ);
    // end FNN
    k_gemm<0, 1><<<dim3(2, YDA + YQ), 512, SMEM_G0>>>(agg, aggq, end_W1, end_b1, nullptr, nullptr,
                                                      nullptr, nullptr, y1, y1q, dstat, dstat1,
                                                      NDA, NQ, YDA, 128, 256);
    k_bnfin2<<<1, 512>>>(dstat, NDA, mu, rstd, dstat1, NQ, mu1, rstd1, 256);
    k_gemm<2, 1><<<dim3(1, YDA + YQ), 512, SMEM_G0>>>(y1, y1q, end_W2, end_b2, mu, rstd, mu1,
                                                      rstd1, y2, y2q, dstat, dstat1, NDA, NQ, YDA,
                                                      256, 128);
    k_bnfin2<<<1, 256>>>(dstat, NDA, mu, rstd, dstat1, NQ, mu1, rstd1, 128);
    k_final_b<<<cdiv((long long)(NDA + NQ) * HD, 256), 256>>>(
        h_da_last, y2, mu, rstd, out_da, h_q_last, y2q, mu1, rstd1, out_q, (long long)NDA * HD,
        (long long)NQ * HD);

    // loss
    k_pesum_b<<<128, 256>>>(PEid, nPE, pe, DEid, nDE, de, src_da, dst_da, el, er, ss);
    k_loss<<<1, 1>>>(pe, de, lenp, out_loss);
}

// round 16
// speedup vs baseline: 1.0355x; 1.0355x over previous
#include <cuda_runtime.h>
#include <math.h>
#include <stdint.h>

#define NDA 100000
#define NQ  20000
#define EDA 1000000
#define EQ  200000
#define BB  64
#define HH  8
#define HD  128
#define HD2 256
#define NEG_SLOPE 2.0f

// ---------------- scratch ----------------
__device__ float g_ft[(size_t)NDA * HD];
__device__ float g_ftq[(size_t)NQ * HD];
__device__ float g_agg[(size_t)NDA * HD];
__device__ float g_aggq[(size_t)NQ * HD];
__device__ float g_y1[(size_t)NDA * HD2];
__device__ float g_y1q[(size_t)NQ * HD2];
__device__ float g_y2[(size_t)NDA * HD];
__device__ float g_y2q[(size_t)NQ * HD];
__device__ float g_el[NDA * HH];
__device__ float g_er[NDA * HH];
__device__ float g_s[NDA * HH];
__device__ float g_elq[NQ * HH];
__device__ float g_erq[NQ * HH];
__device__ float g_sq2[NQ * HH];
__device__ float g_eb[NQ];
__device__ int   g_deg[NDA];
__device__ int   g_coff[NDA];
__device__ int   g_cursor[NDA];
__device__ int   g_srcs[EDA];
__device__ int   g_bsum[256];
__device__ int   g_degq[NQ];
__device__ int   g_coffq[NQ];
__device__ int   g_cursorq[NQ];
__device__ int   g_srcsq[EQ];
__device__ int   g_bsumq[256];
__device__ float g_glq[BB * HD];
__device__ float g_t1[BB * HD2];
__device__ float g_t2[BB * HD2];
__device__ float g_Q[BB * HD2];
__device__ float g_gsumq[BB];
__device__ float g_accq[BB * 4];
__device__ float g_accda[BB * 4];
__device__ float g_aabq[BB * 2];
__device__ float g_aabda[BB * 2];
__device__ double g_dstat[1024];
__device__ float g_mu[512];
__device__ float g_rstd[512];
__device__ float g_pe[HH];
__device__ float g_de[HH];

__device__ __forceinline__ float eluf(float x) { return x > 0.f ? x : expm1f(x); }

__device__ __forceinline__ uint32_t smem_u32(const void* p) {
    uint32_t a;
    asm("{ .reg .u64 t; cvta.to.shared.u64 t, %1; cvt.u32.u64 %0, t; }" : "=r"(a) : "l"(p));
    return a;
}
__device__ __forceinline__ uint32_t f2tf(float x) {
    uint32_t r;
    asm("cvt.rna.tf32.f32 %0, %1;" : "=r"(r) : "f"(x));
    return r;
}
__device__ __forceinline__ void mma8(float* d, const uint32_t* a, const uint32_t* b) {
    asm volatile(
        "mma.sync.aligned.m16n8k8.row.col.f32.tf32.tf32.f32 "
        "{%0,%1,%2,%3}, {%4,%5,%6,%7}, {%8,%9}, {%0,%1,%2,%3};\n"
        : "+f"(d[0]), "+f"(d[1]), "+f"(d[2]), "+f"(d[3])
        : "r"(a[0]), "r"(a[1]), "r"(a[2]), "r"(a[3]), "r"(b[0]), "r"(b[1]));
}

#define AOFF(buf) ((buf) * 4608)
#define WOFF(buf) (9216 + (buf) * 4224)
#define A2OFF(buf) (17664 + (buf) * 4608)
#define SMEM_G0 ((9216 + 8448) * 4)
#define SMEM_G1 ((9216 + 8448 + 9216) * 4)

__device__ __forceinline__ void stage_issue_r(uint32_t sb, int buf, const float* __restrict__ A,
                                              const float* __restrict__ A2, bool blend,
                                              const float* __restrict__ W, int rowBase,
                                              int colBase, int k0, int n, int K, int NC,
                                              int tid) {
    uint32_t abase = sb + AOFF(buf) * 4;
    uint32_t wbase = sb + WOFF(buf) * 4;
#pragma unroll
    for (int q = 0; q < 4; q++) {
        int id = tid + q * 256;
        int r = id >> 3, kq = id & 7;
        int grow = rowBase + r;
        const float* src = A + (size_t)grow * K + k0 + kq * 4;
        uint32_t dst = abase + (r * 36 + kq * 4) * 4;
        int sz = grow < n ? 16 : 0;
        asm volatile("cp.async.ca.shared.global [%0], [%1], 16, %2;" ::"r"(dst), "l"(src), "r"(sz)
                     : "memory");
    }
    if (blend) {
        uint32_t a2base = sb + A2OFF(buf) * 4;
#pragma unroll
        for (int q = 0; q < 4; q++) {
            int id = tid + q * 256;
            int r = id >> 3, kq = id & 7;
            int grow = rowBase + r;
            const float* src = A2 + (size_t)grow * K + k0 + kq * 4;
            uint32_t dst = a2base + (r * 36 + kq * 4) * 4;
            int sz = grow < n ? 16 : 0;
            asm volatile("cp.async.ca.shared.global [%0], [%1], 16, %2;" ::"r"(dst), "l"(src),
                         "r"(sz)
                         : "memory");
        }
    }
#pragma unroll
    for (int q = 0; q < 4; q++) {
        int id = tid + q * 256;
        int kk = id >> 5, nq = id & 31;
        const float* src = W + (size_t)(k0 + kk) * NC + colBase + nq * 4;
        uint32_t dst = wbase + (kk * 132 + nq * 4) * 4;
        asm volatile("cp.async.ca.shared.global [%0], [%1], 16;" ::"r"(dst), "l"(src) : "memory");
    }
    asm volatile("cp.async.commit_group;" ::: "memory");
}

// ---------------- mega W_L GEMM: feat subproblems emit el/er only ----------------
__global__ void __launch_bounds__(256, 2) k_gemmW(
    const float* __restrict__ hdl, const float* __restrict__ hql,
    const float* __restrict__ hd0, const float* __restrict__ hq0,
    const float* __restrict__ aabda, const float* __restrict__ aabq,
    const int* __restrict__ gid_da, const int* __restrict__ gid_q,
    const float* __restrict__ W, const float* __restrict__ bias,
    const float* __restrict__ Qb,
    float* ft, float* ftq,
    float* el, float* er, float* elq, float* erq, int YDA, int YQ) {
    extern __shared__ float smf[];
    const uint32_t sb = smem_u32(smf);
    const int tid = threadIdx.x;
    const int lane = tid & 31;
    const int wid = tid >> 5;
    const int warp_m = wid >> 2;
    const int warp_n = wid & 3;

    int by = blockIdx.y;
    const float *A1, *A2, *acoef;
    const int* gid;
    float *C, *elo, *ero;
    int n;
    bool blend;
    if (by < YDA) {
        A1 = hdl; A2 = nullptr; acoef = nullptr; gid = gid_da; C = nullptr; elo = el; ero = er;
        n = NDA; blend = false;
    } else if (by < YDA + YQ) {
        by -= YDA;
        A1 = hql; A2 = nullptr; acoef = nullptr; gid = gid_q; C = nullptr; elo = elq; ero = erq;
        n = NQ; blend = false;
    } else if (by < 2 * YDA + YQ) {
        by -= YDA + YQ;
        A1 = hd0; A2 = hdl; acoef = aabda; gid = gid_da; C = ft; elo = nullptr; ero = nullptr;
        n = NDA; blend = true;
    } else {
        by -= 2 * YDA + YQ;
        A1 = hq0; A2 = hql; acoef = aabq; gid = gid_q; C = ftq; elo = nullptr; ero = nullptr;
        n = NQ; blend = true;
    }
    const int rowBase = by * 128;
    const int g4 = lane >> 2;
    const int t4 = lane & 3;

    float c0 = 0.f, c1 = 0.f;
    if (blend) {
        int rr = rowBase + (tid >> 1);
        if (rr < n) {
            int g = gid[rr];
            c0 = acoef[2 * g];
            c1 = acoef[2 * g + 1];
        }
    }

    stage_issue_r(sb, 0, A1, A2, blend, W, rowBase, 0, 0, n, 128, 128, tid);
    stage_issue_r(sb, 1, A1, A2, blend, W, rowBase, 0, 32, n, 128, 128, tid);

    float acc[4][4][4];
#pragma unroll
    for (int mi = 0; mi < 4; mi++)
#pragma unroll
        for (int ni = 0; ni < 4; ni++)
#pragma unroll
            for (int r = 0; r < 4; r++) acc[mi][ni][r] = 0.f;

    const int nk = 4;
    for (int i = 0; i < nk; i++) {
        int p = i & 1;
        if (i + 1 < nk)
            asm volatile("cp.async.wait_group 1;" ::: "memory");
        else
            asm volatile("cp.async.wait_group 0;" ::: "memory");
        __syncthreads();
        if (blend) {
            float* a = smf + AOFF(p) + (tid >> 1) * 36 + (tid & 1) * 16;
            const float* b2 = smf + A2OFF(p) + (tid >> 1) * 36 + (tid & 1) * 16;
#pragma unroll
            for (int j = 0; j < 16; j++) a[j] = c0 * a[j] + c1 * b2[j];
            __syncthreads();
        }
        const float* Af = smf + AOFF(p);
        const float* Wf = smf + WOFF(p);
#pragma unroll
        for (int ks = 0; ks < 4; ks++) {
            int kk = ks * 8;
            uint32_t a[4][4];
#pragma unroll
            for (int mi = 0; mi < 4; mi++) {
                int r = warp_m * 64 + mi * 16 + g4;
                a[mi][0] = f2tf(Af[r * 36 + kk + t4]);
                a[mi][1] = f2tf(Af[(r + 8) * 36 + kk + t4]);
                a[mi][2] = f2tf(Af[r * 36 + kk + t4 + 4]);
                a[mi][3] = f2tf(Af[(r + 8) * 36 + kk + t4 + 4]);
            }
            uint32_t b[4][2];
#pragma unroll
            for (int ni = 0; ni < 4; ni++) {
                int c = warp_n * 32 + ni * 8 + g4;
                b[ni][0] = f2tf(Wf[(kk + t4) * 132 + c]);
                b[ni][1] = f2tf(Wf[(kk + t4 + 4) * 132 + c]);
            }
#pragma unroll
            for (int mi = 0; mi < 4; mi++)
#pragma unroll
                for (int ni = 0; ni < 4; ni++) mma8(acc[mi][ni], a[mi], b[ni]);
        }
        __syncthreads();
        if (i + 2 < nk)
            stage_issue_r(sb, p, A1, A2, blend, W, rowBase, 0, (i + 2) * 32, n, 128, 128, tid);
    }

    float* sC = smf;
#pragma unroll
    for (int mi = 0; mi < 4; mi++) {
        int lr0 = warp_m * 64 + mi * 16 + g4;
        int lr1 = lr0 + 8;
        int r0 = rowBase + lr0, r1 = rowBase + lr1;
#pragma unroll
        for (int ni = 0; ni < 4; ni++) {
            int c = warp_n * 32 + ni * 8 + t4 * 2;
            float b0 = bias[c], b1 = bias[c + 1];
            float v0 = acc[mi][ni][0] + b0, v1 = acc[mi][ni][1] + b1;
            float v2 = acc[mi][ni][2] + b0, v3 = acc[mi][ni][3] + b1;
            if (elo) {
                sC[lr0 * 132 + c] = v0;
                sC[lr0 * 132 + c + 1] = v1;
                sC[lr1 * 132 + c] = v2;
                sC[lr1 * 132 + c + 1] = v3;
            } else {
                if (r0 < n) {
                    C[(size_t)r0 * HD + c] = v0;
                    C[(size_t)r0 * HD + c + 1] = v1;
                }
                if (r1 < n) {
                    C[(size_t)r1 * HD + c] = v2;
                    C[(size_t)r1 * HD + c + 1] = v3;
                }
            }
        }
    }
    if (elo) {
        __syncthreads();
        int il = tid >> 1;
        int hbase = (tid & 1) * 4;
        int grow = rowBase + il;
        if (grow < n) {
            int gg = gid[grow];
            const float* f = sC + il * 132;
            float sl4[4], sr4[4];
#pragma unroll
            for (int hh = 0; hh < 4; hh++) {
                int h = hbase + hh;
                const float* q = Qb + (size_t)gg * HD2 + h * 32;
                float sl = 0.f, sr = 0.f;
#pragma unroll
                for (int c = 0; c < 16; c++) {
                    float fv = f[h * 16 + c];
                    sl = fmaf(fv, q[c], sl);
                    sr = fmaf(fv, q[16 + c], sr);
                }
                sl4[hh] = sl;
                sr4[hh] = sr;
            }
            *(float4*)(elo + (size_t)grow * HH + hbase) =
                make_float4(sl4[0], sl4[1], sl4[2], sl4[3]);
            *(float4*)(ero + (size_t)grow * HH + hbase) =
                make_float4(sr4[0], sr4[1], sr4[2], sr4[3]);
        }
    }
}

// ---------------- two-problem GEMM (Qf + end layers) ----------------
template <int AMODE, int STAT>
__global__ void __launch_bounds__(256, 2) k_gemm(
    const float* __restrict__ A1a, const float* __restrict__ A1b,
    const float* __restrict__ W, const float* __restrict__ bias,
    const float* __restrict__ mu0, const float* __restrict__ rstd0,
    const float* __restrict__ mu1, const float* __restrict__ rstd1,
    float* Ca, float* Cb, double* ds0, double* ds1,
    int na, int nb, int yb, int K, int NC) {
    extern __shared__ float smf[];
    __shared__ float sstat[256];
    const uint32_t sb = smem_u32(smf);
    const int tid = threadIdx.x;
    const int lane = tid & 31;
    const int wid = tid >> 5;
    const int warp_m = wid >> 2;
    const int warp_n = wid & 3;

    int by = blockIdx.y;
    const float *A1, *mu, *rstd;
    float* C;
    double* dstat;
    int n;
    if (by < yb) {
        A1 = A1a; C = Ca; dstat = ds0; n = na; mu = mu0; rstd = rstd0;
    } else {
        by -= yb;
        A1 = A1b; C = Cb; dstat = ds1; n = nb; mu = mu1; rstd = rstd1;
    }
    const int rowBase = by * 128;
    const int colBase = blockIdx.x * 128;
    const int g4 = lane >> 2;
    const int t4 = lane & 3;

    if (STAT && tid < 256) sstat[tid] = 0.f;

    stage_issue_r(sb, 0, A1, nullptr, false, W, rowBase, colBase, 0, n, K, NC, tid);
    stage_issue_r(sb, 1, A1, nullptr, false, W, rowBase, colBase, 32, n, K, NC, tid);

    float acc[4][4][4];
#pragma unroll
    for (int mi = 0; mi < 4; mi++)
#pragma unroll
        for (int ni = 0; ni < 4; ni++)
#pragma unroll
            for (int r = 0; r < 4; r++) acc[mi][ni][r] = 0.f;

    const int nk = K >> 5;
    for (int i = 0; i < nk; i++) {
        int p = i & 1;
        if (i + 1 < nk)
            asm volatile("cp.async.wait_group 1;" ::: "memory");
        else
            asm volatile("cp.async.wait_group 0;" ::: "memory");
        __syncthreads();
        if (AMODE == 2) {
            int kg = i * 32 + (tid & 1) * 16;
            float* a = smf + AOFF(p) + (tid >> 1) * 36 + (tid & 1) * 16;
#pragma unroll
            for (int j = 0; j < 16; j++) a[j] = eluf((a[j] - mu[kg + j]) * rstd[kg + j]);
            __syncthreads();
        }
        const float* Af = smf + AOFF(p);
        const float* Wf = smf + WOFF(p);
#pragma unroll
        for (int ks = 0; ks < 4; ks++) {
            int kk = ks * 8;
            uint32_t a[4][4];
#pragma unroll
            for (int mi = 0; mi < 4; mi++) {
                int r = warp_m * 64 + mi * 16 + g4;
                a[mi][0] = f2tf(Af[r * 36 + kk + t4]);
                a[mi][1] = f2tf(Af[(r + 8) * 36 + kk + t4]);
                a[mi][2] = f2tf(Af[r * 36 + kk + t4 + 4]);
                a[mi][3] = f2tf(Af[(r + 8) * 36 + kk + t4 + 4]);
            }
            uint32_t b[4][2];
#pragma unroll
            for (int ni = 0; ni < 4; ni++) {
                int c = warp_n * 32 + ni * 8 + g4;
                b[ni][0] = f2tf(Wf[(kk + t4) * 132 + c]);
                b[ni][1] = f2tf(Wf[(kk + t4 + 4) * 132 + c]);
            }
#pragma unroll
            for (int mi = 0; mi < 4; mi++)
#pragma unroll
                for (int ni = 0; ni < 4; ni++) mma8(acc[mi][ni], a[mi], b[ni]);
        }
        __syncthreads();
        if (i + 2 < nk)
            stage_issue_r(sb, p, A1, nullptr, false, W, rowBase, colBase, (i + 2) * 32, n, K, NC,
                          tid);
    }

    float cs[8], cq[8];
#pragma unroll
    for (int i = 0; i < 8; i++) { cs[i] = 0.f; cq[i] = 0.f; }

#pragma unroll
    for (int mi = 0; mi < 4; mi++) {
        int r0 = rowBase + warp_m * 64 + mi * 16 + g4;
        int r1 = r0 + 8;
#pragma unroll
        for (int ni = 0; ni < 4; ni++) {
            int c = colBase + warp_n * 32 + ni * 8 + t4 * 2;
            float b0 = bias[c], b1 = bias[c + 1];
            if (r0 < n) {
                float v0 = acc[mi][ni][0] + b0, v1 = acc[mi][ni][1] + b1;
                C[(size_t)r0 * NC + c] = v0;
                C[(size_t)r0 * NC + c + 1] = v1;
                if (STAT) {
                    cs[ni * 2] += v0; cq[ni * 2] += v0 * v0;
                    cs[ni * 2 + 1] += v1; cq[ni * 2 + 1] += v1 * v1;
                }
            }
            if (r1 < n) {
                float v2 = acc[mi][ni][2] + b0, v3 = acc[mi][ni][3] + b1;
                C[(size_t)r1 * NC + c] = v2;
                C[(size_t)r1 * NC + c + 1] = v3;
                if (STAT) {
                    cs[ni * 2] += v2; cq[ni * 2] += v2 * v2;
                    cs[ni * 2 + 1] += v3; cq[ni * 2 + 1] += v3 * v3;
                }
            }
        }
    }
    if (STAT) {
#pragma unroll
        for (int i = 0; i < 8; i++) {
            float s = cs[i], q = cq[i];
            s += __shfl_down_sync(0xffffffffu, s, 16);
            q += __shfl_down_sync(0xffffffffu, q, 16);
            s += __shfl_down_sync(0xffffffffu, s, 8);
            q += __shfl_down_sync(0xffffffffu, q, 8);
            s += __shfl_down_sync(0xffffffffu, s, 4);
            q += __shfl_down_sync(0xffffffffu, q, 4);
            if (g4 == 0) {
                int c = warp_n * 32 + (i >> 1) * 8 + t4 * 2 + (i & 1);
                atomicAdd(&sstat[c], s);
                atomicAdd(&sstat[128 + c], q);
            }
        }
        __syncthreads();
        if (tid < 128) {
            atomicAdd(&dstat[colBase + tid], (double)sstat[tid]);
            atomicAdd(&dstat[256 + colBase + tid], (double)sstat[128 + tid]);
        }
    }
}

// ---------------- fills ----------------
__global__ void k_zero0(float* glq, float* gsumq, float* accq, float* accda, float* pe, float* de,
                        int* dga, int* dgb, double* dstat) {
    int i = blockIdx.x * blockDim.x + threadIdx.x;
    if (i < NDA) dga[i] = 0;
    if (i < NQ) dgb[i] = 0;
    if (i < BB * HD) glq[i] = 0.f;
    if (i < BB) gsumq[i] = 0.f;
    if (i < BB * 4) { accq[i] = 0.f; accda[i] = 0.f; }
    if (i < HH) { pe[i] = 0.f; de[i] = 0.f; }
    if (i < 1024) dstat[i] = 0.0;
}

// ---------------- gate kernels ----------------
__global__ void k_gap_pool(const float* __restrict__ M, const int* __restrict__ gid,
                           const float* __restrict__ e, const float* __restrict__ gsum,
                           float* pool, int n) {
    int w = (blockIdx.x * blockDim.x + threadIdx.x) >> 5;
    int lane = threadIdx.x & 31;
    if (w >= n) return;
    int b = gid[w];
    float wt = e[w] / gsum[b];
    const float* row = M + (size_t)w * HD;
#pragma unroll
    for (int j = lane; j < HD; j += 32) atomicAdd(&pool[b * HD + j], wt * row[j]);
}

__global__ void __launch_bounds__(1024) k_gapdots_b(
    const float* __restrict__ h0a, const float* __restrict__ hla, const int* __restrict__ gia,
    float* acca,
    const float* __restrict__ h0b, const float* __restrict__ hlb, const int* __restrict__ gib,
    float* accb,
    const float* __restrict__ w1, const float* __restrict__ b1, const float* __restrict__ w2,
    const float* __restrict__ b2, const float* __restrict__ qc,
    const float* __restrict__ wq, const float* __restrict__ bq, float* ebuf, float* gsumq,
    int ybreak) {
    __shared__ int sgid[32];
    __shared__ float sv[32][5];
    const float *M1, *M2;
    const int* gid;
    float* acc;
    int nodeBase;
    bool isq = (int)blockIdx.x >= ybreak;
    if (!isq) {
        M1 = h0a; M2 = hla; gid = gia; acc = acca; nodeBase = blockIdx.x * 32;
    } else {
        M1 = h0b; M2 = hlb; gid = gib; acc = accb; nodeBase = (blockIdx.x - ybreak) * 32;
    }
    int wid = threadIdx.x >> 5, lane = threadIdx.x & 31;
    int node = nodeBase + wid;
    {
        float4 a = ((const float4*)(M1 + (size_t)node * HD))[lane];
        float4 bb = ((const float4*)(M2 + (size_t)node * HD))[lane];
        float4 w1v = ((const float4*)w1)[lane];
        float4 w2v = ((const float4*)w2)[lane];
        float4 qv = ((const float4*)qc)[lane];
        float s1 = a.x * w1v.x + a.y * w1v.y + a.z * w1v.z + a.w * w1v.w;
        float q1 = a.x * qv.x + a.y * qv.y + a.z * qv.z + a.w * qv.w;
        float s2 = bb.x * w2v.x + bb.y * w2v.y + bb.z * w2v.z + bb.w * w2v.w;
        float q2 = bb.x * qv.x + bb.y * qv.y + bb.z * qv.z + bb.w * qv.w;
        float s3 = 0.f;
        if (isq) {
            float4 wqv = ((const float4*)wq)[lane];
            s3 = bb.x * wqv.x + bb.y * wqv.y + bb.z * wqv.z + bb.w * wqv.w;
        }
#pragma unroll
        for (int o = 16; o; o >>= 1) {
            s1 += __shfl_down_sync(0xffffffffu, s1, o);
            q1 += __shfl_down_sync(0xffffffffu, q1, o);
            s2 += __shfl_down_sync(0xffffffffu, s2, o);
            q2 += __shfl_down_sync(0xffffffffu, q2, o);
            s3 += __shfl_down_sync(0xffffffffu, s3, o);
        }
        if (lane == 0) {
            float e1 = expf(s1 + b1[0]), e2 = expf(s2 + b2[0]);
            sgid[wid] = gid[node];
            sv[wid][0] = e1; sv[wid][1] = e1 * q1; sv[wid][2] = e2; sv[wid][3] = e2 * q2;
            if (isq) {
                float e3 = expf(s3 + bq[0]);
                ebuf[node] = e3;
                sv[wid][4] = e3;
            }
        }
    }
    __syncthreads();
    int ncomp = isq ? 5 : 4;
    if ((int)threadIdx.x < ncomp) {
        int comp = threadIdx.x;
        int cur = -2;
        float a = 0.f;
        for (int i = 0; i < 32; i++) {
            int g = sgid[i];
            if (g != cur) {
                if (cur >= 0) {
                    if (comp < 4) atomicAdd(&acc[cur * 4 + comp], a);
                    else atomicAdd(&gsumq[cur], a);
                }
                cur = g;
                a = 0.f;
            }
            a += sv[i][comp];
        }
        if (cur >= 0) {
            if (comp < 4) atomicAdd(&acc[cur * 4 + comp], a);
            else atomicAdd(&gsumq[cur], a);
        }
    }
}

// ---------------- CSR build (vectorized) ----------------
__global__ void k_hist_b(const int4* __restrict__ dsta, int* dga, const int4* __restrict__ dstb,
                         int* dgb, int E4a, int E4b) {
    int t = blockIdx.x * blockDim.x + threadIdx.x;
    if (t < E4a) {
        int4 d = __ldg(&dsta[t]);
        atomicAdd(&dga[d.x], 1);
        atomicAdd(&dga[d.y], 1);
        atomicAdd(&dga[d.z], 1);
        atomicAdd(&dga[d.w], 1);
    } else {
        t -= E4a;
        if (t < E4b) {
            int4 d = __ldg(&dstb[t]);
            atomicAdd(&dgb[d.x], 1);
            atomicAdd(&dgb[d.y], 1);
            atomicAdd(&dgb[d.z], 1);
            atomicAdd(&dgb[d.w], 1);
        }
    }
}
__global__ void k_scan1_b(const int* __restrict__ dga, int* coffa, int* bsuma,
                          const int* __restrict__ dgb, int* coffb, int* bsumb, int na, int nb,
                          int nba) {
    __shared__ int sh[512];
    const int* dg;
    int *outp, *bsum;
    int n, bid;
    if ((int)blockIdx.x < nba) { dg = dga; outp = coffa; bsum = bsuma; n = na; bid = blockIdx.x; }
    else { dg = dgb; outp = coffb; bsum = bsumb; n = nb; bid = blockIdx.x - nba; }
    int base = bid * 512, t = threadIdx.x;
    int v0 = (base + t < n) ? dg[base + t] : 0;
    int v1 = (base + 256 + t < n) ? dg[base + 256 + t] : 0;
    sh[t] = v0; sh[t + 256] = v1;
    __syncthreads();
    for (int off = 1; off < 512; off <<= 1) {
        int i0 = t, i1 = t + 256;
        int n0 = sh[i0] + ((i0 >= off) ? sh[i0 - off] : 0);
        int n1 = sh[i1] + ((i1 >= off) ? sh[i1 - off] : 0);
        __syncthreads();
        sh[i0] = n0; sh[i1] = n1;
        __syncthreads();
    }
    if (base + t < n) outp[base + t] = sh[t] - v0;
    if (base + 256 + t < n) outp[base + 256 + t] = sh[t + 256] - v1;
    if (t == 0) bsum[bid] = sh[511];
}
__global__ void k_scan2_comb(int* bsuma, int nba, int* bsumb, int nbb,
                             const float* __restrict__ accq, float* aabq,
                             const float* __restrict__ accda, float* aabda) {
    __shared__ int sh[256];
    if (blockIdx.x < 2) {
        int* bsum = blockIdx.x == 0 ? bsuma : bsumb;
        int nb = blockIdx.x == 0 ? nba : nbb;
        int t = threadIdx.x;
        int v = (t < nb) ? bsum[t] : 0;
        sh[t] = v;
        __syncthreads();
        for (int off = 1; off < 256; off <<= 1) {
            int x = sh[t] + ((t >= off) ? sh[t - off] : 0);
            __syncthreads();
            sh[t] = x;
            __syncthreads();
        }
        if (t < nb) bsum[t] = sh[t] - v;
        return;
    }
    int t = threadIdx.x;
    if (t < 128) {
        const float* acc = t < BB ? accq : accda;
        float* aab = t < BB ? aabq : aabda;
        int b = t & (BB - 1);
        float d1 = acc[b * 4 + 1] / acc[b * 4 + 0];
        float d2 = acc[b * 4 + 3] / acc[b * 4 + 2];
        float mm = fmaxf(d1, d2);
        float e1 = expf(d1 - mm), e2 = expf(d2 - mm);
        float ss = e1 + e2;
        aab[2 * b] = e1 / ss;
        aab[2 * b + 1] = e2 / ss;
    }
}
__global__ void k_scan3_b(int* coffa, int* cura, const int* __restrict__ bsuma, int* coffb,
                          int* curb, const int* __restrict__ bsumb, int na, int nb) {
    int i = blockIdx.x * blockDim.x + threadIdx.x;
    if (i < na) {
        int v = coffa[i] + bsuma[i >> 9];
        coffa[i] = v;
        cura[i] = v;
    } else {
        i -= na;
        if (i < nb) {
            int v = coffb[i] + bsumb[i >> 9];
            coffb[i] = v;
            curb[i] = v;
        }
    }
}
__global__ void k_scatter_b(const int4* __restrict__ srca, const int4* __restrict__ dsta,
                            int* cura, int* srcsa, const int4* __restrict__ srcb,
                            const int4* __restrict__ dstb, int* curb, int* srcsb, int E4a,
                            int E4b) {
    int t = blockIdx.x * blockDim.x + threadIdx.x;
    if (t < E4a) {
        int4 d = __ldg(&dsta[t]);
        int4 s = __ldg(&srca[t]);
        srcsa[atomicAdd(&cura[d.x], 1)] = s.x;
        srcsa[atomicAdd(&cura[d.y], 1)] = s.y;
        srcsa[atomicAdd(&cura[d.z], 1)] = s.z;
        srcsa[atomicAdd(&cura[d.w], 1)] = s.w;
    } else {
        t -= E4a;
        if (t < E4b) {
            int4 d = __ldg(&dstb[t]);
            int4 s = __ldg(&srcb[t]);
            srcsb[atomicAdd(&curb[d.x], 1)] = s.x;
            srcsb[atomicAdd(&curb[d.y], 1)] = s.y;
            srcsb[atomicAdd(&curb[d.z], 1)] = s.z;
            srcsb[atomicAdd(&curb[d.w], 1)] = s.w;
        }
    }
}

// ---------------- batched single-pass edge softmax + aggregation ----------------
__global__ void k_node_agg_b(const int* __restrict__ srcsa, const int* __restrict__ coffa,
                             const int* __restrict__ dga, const float* __restrict__ ela,
                             const float* __restrict__ era, const float* __restrict__ fta,
                             float* agga, float* sa, const int* __restrict__ srcsb,
                             const int* __restrict__ coffb, const int* __restrict__ dgb,
                             const float* __restrict__ elb, const float* __restrict__ erb,
                             const float* __restrict__ ftb, float* aggb, float* sb2, int na,
                             int nb) {
    int w = (blockIdx.x * blockDim.x + threadIdx.x) >> 5;
    int lane = threadIdx.x & 31;
    const int *srcs, *coff, *dg;
    const float *el, *er, *ft;
    float *agg, *s;
    if (w < na) {
        srcs = srcsa; coff = coffa; dg = dga; el = ela; er = era; ft = fta; agg = agga; s = sa;
    } else {
        w -= na;
        if (w >= nb) return;
        srcs = srcsb; coff = coffb; dg = dgb; el = elb; er = erb; ft = ftb; agg = aggb; s = sb2;
    }
    int h = lane >> 2;
    int off = coff[w], d = dg[w];
    float erv = er[w * HH + h];
    float wsum = 0.f;
    float4 acc = make_float4(0.f, 0.f, 0.f, 0.f);
    int sn_next = (d > 0) ? __ldg(&srcs[off]) : 0;
#pragma unroll 4
    for (int j = 0; j < d; j++) {
        int sn = sn_next;
        if (j + 1 < d) sn_next = __ldg(&srcs[off + j + 1]);
        float elv = __ldg(&el[sn * HH + h]);
        float4 fv = __ldg((const float4*)(ft + (size_t)sn * HD + lane * 4));
        float v = elv + erv;
        v = v > 0.f ? v : NEG_SLOPE * v;
        float wt = expf(v);
        wsum += wt;
        acc.x = fmaf(wt, fv.x, acc.x);
        acc.y = fmaf(wt, fv.y, acc.y);
        acc.z = fmaf(wt, fv.z, acc.z);
        acc.w = fmaf(wt, fv.w, acc.w);
    }
    float inv = wsum > 0.f ? 1.f / wsum : 0.f;
    acc.x *= inv; acc.y *= inv; acc.z *= inv; acc.w *= inv;
    *(float4*)(agg + (size_t)w * HD + lane * 4) = acc;
    if ((lane & 3) == 0) s[w * HH + h] = wsum;
}

// ---------------- bn finalize (self-zeroing) / apply ----------------
__global__ void k_bnfin2(double* st0, int n0, float* mu0, float* rstd0, double* st1, int n1,
                         float* mu1, float* rstd1, int C) {
    int t = threadIdx.x;
    double* st;
    float *mu, *rstd;
    int n, c;
    if (t < C) { st = st0; mu = mu0; rstd = rstd0; n = n0; c = t; }
    else { st = st1; mu = mu1; rstd = rstd1; n = n1; c = t - C; }
    double m = st[c] / n;
    double v = st[256 + c] / n - m * m;
    if (v < 0.0) v = 0.0;
    mu[c] = (float)m;
    rstd[c] = (float)(1.0 / sqrt(v + 1e-5));
    st[c] = 0.0;
    st[256 + c] = 0.0;
}
__global__ void k_bnelu(const float* __restrict__ Y, const float* __restrict__ mu,
                        const float* __restrict__ rstd, float* outp, long long total, int C) {
    long long i = (long long)blockIdx.x * blockDim.x + threadIdx.x;
    if (i < total) {
        int c = (int)(i % C);
        outp[i] = eluf((Y[i] - mu[c]) * rstd[c]);
    }
}
__global__ void k_final_b(const float* __restrict__ hla, const float* __restrict__ y2a,
                          const float* __restrict__ mu0, const float* __restrict__ rstd0,
                          float* outa, const float* __restrict__ hlb,
                          const float* __restrict__ y2b, const float* __restrict__ mu1,
                          const float* __restrict__ rstd1, float* outb, long long ta,
                          long long tb) {
    long long i = (long long)blockIdx.x * blockDim.x + threadIdx.x;
    const float *hl, *Y, *mu, *rstd;
    float* outp;
    if (i < ta) { hl = hla; Y = y2a; mu = mu0; rstd = rstd0; outp = outa; }
    else {
        i -= ta;
        if (i >= tb) return;
        hl = hlb; Y = y2b; mu = mu1; rstd = rstd1; outp = outb;
    }
    int c = (int)(i & (HD - 1));
    outp[i] = hl[i] + eluf((Y[i] - mu[c]) * rstd[c]);
}

// ---------------- loss ----------------
__global__ void k_pesum_b(const int* __restrict__ peid, int npe, float* peout,
                          const int* __restrict__ deid, int nde, float* deout,
                          const int* __restrict__ src, const int* __restrict__ dst,
                          const float* __restrict__ el, const float* __restrict__ er,
                          const float* __restrict__ s) {
    const int* ids;
    float* out8;
    int nids, bid;
    int half = gridDim.x / 2;
    if ((int)blockIdx.x < half) { ids = peid; out8 = peout; nids = npe; bid = blockIdx.x; }
    else { ids = deid; out8 = deout; nids = nde; bid = blockIdx.x - half; }
    float acc[HH];
#pragma unroll
    for (int h = 0; h < HH; h++) acc[h] = 0.f;
    for (int i = bid * blockDim.x + threadIdx.x; i < nids; i += half * blockDim.x) {
        int e = ids[i];
        int se = src[e] * HH, de = dst[e] * HH;
#pragma unroll
        for (int h = 0; h < HH; h++) {
            float v = el[se + h] + er[de + h];
            v = v > 0.f ? v : NEG_SLOPE * v;
            acc[h] += expf(v) / s[de + h];
        }
    }
#pragma unroll
    for (int h = 0; h < HH; h++)
#pragma unroll
        for (int o = 16; o; o >>= 1) acc[h] += __shfl_down_sync(0xffffffffu, acc[h], o);
    if ((threadIdx.x & 31) == 0)
#pragma unroll
        for (int h = 0; h < HH; h++) atomicAdd(&out8[h], acc[h]);
}
__global__ void k_loss(const float* pe, const float* de, const int* lenp, float* outp) {
    float sum = 0.f;
#pragma unroll
    for (int h = 0; h < HH; h++) sum += pe[h] - de[h];
    outp[0] = -sum / (8.0f * (float)lenp[0]);
}

// ---------------- host ----------------
static inline int cdiv(long long a, long long b) { return (int)((a + b - 1) / b); }

extern "C" void kernel_launch(void* const* d_in, const int* in_sizes, int n_in, void* d_out,
                              int out_size) {
    const float* h_da_last = (const float*)d_in[0];
    const float* h_q_last  = (const float*)d_in[1];
    const float* h_da_0    = (const float*)d_in[2];
    const float* h_q_0     = (const float*)d_in[3];
    const float* W_L       = (const float*)d_in[4];
    const float* b_L       = (const float*)d_in[5];
    const float* gateq_W   = (const float*)d_in[6];
    const float* gateq_b   = (const float*)d_in[7];
    const float* gate1_W   = (const float*)d_in[8];
    const float* gate1_b   = (const float*)d_in[9];
    const float* gate2_W   = (const float*)d_in[10];
    const float* gate2_b   = (const float*)d_in[11];
    const float* Q_comb    = (const float*)d_in[12];
    const float* Qf_W1     = (const float*)d_in[13];
    const float* Qf_b1     = (const float*)d_in[14];
    const float* Qf_W2     = (const float*)d_in[15];
    const float* Qf_b2     = (const float*)d_in[16];
    const float* end_W1    = (const float*)d_in[17];
    const float* end_b1    = (const float*)d_in[18];
    const float* end_W2    = (const float*)d_in[19];
    const float* end_b2    = (const float*)d_in[20];
    const int* src_da = (const int*)d_in[21];
    const int* dst_da = (const int*)d_in[22];
    const int* src_q  = (const int*)d_in[23];
    const int* dst_q  = (const int*)d_in[24];
    const int* gid_da = (const int*)d_in[25];
    const int* gid_q  = (const int*)d_in[26];
    const int* PEid   = (const int*)d_in[27];
    const int* DEid   = (const int*)d_in[28];
    const int* lenp   = (const int*)d_in[29];
    int nPE = in_sizes[27], nDE = in_sizes[28];

    float* outp = (float*)d_out;
    float* out_da = outp;
    float* out_q = outp + (long long)NDA * HD;
    float* out_loss = outp + (long long)NDA * HD + (long long)NQ * HD;

    float *ft, *ftq, *agg, *aggq, *y1, *y1q, *y2, *y2q;
    float *el, *er, *ss, *elq, *erq, *sq2, *eb;
    float *glq, *t1, *t2, *Qb, *gsumq, *accq, *accda, *aabq, *aabda, *mu, *rstd, *pe, *de;
    double* dstat;
    int *dg, *coff, *cursor, *srcs, *bsum, *dgq, *coffq, *cursorq, *srcsq, *bsumq;
    cudaGetSymbolAddress((void**)&ft, g_ft);
    cudaGetSymbolAddress((void**)&ftq, g_ftq);
    cudaGetSymbolAddress((void**)&agg, g_agg);
    cudaGetSymbolAddress((void**)&aggq, g_aggq);
    cudaGetSymbolAddress((void**)&y1, g_y1);
    cudaGetSymbolAddress((void**)&y1q, g_y1q);
    cudaGetSymbolAddress((void**)&y2, g_y2);
    cudaGetSymbolAddress((void**)&y2q, g_y2q);
    cudaGetSymbolAddress((void**)&el, g_el);
    cudaGetSymbolAddress((void**)&er, g_er);
    cudaGetSymbolAddress((void**)&ss, g_s);
    cudaGetSymbolAddress((void**)&elq, g_elq);
    cudaGetSymbolAddress((void**)&erq, g_erq);
    cudaGetSymbolAddress((void**)&sq2, g_sq2);
    cudaGetSymbolAddress((void**)&eb, g_eb);
    cudaGetSymbolAddress((void**)&glq, g_glq);
    cudaGetSymbolAddress((void**)&t1, g_t1);
    cudaGetSymbolAddress((void**)&t2, g_t2);
    cudaGetSymbolAddress((void**)&Qb, g_Q);
    cudaGetSymbolAddress((void**)&gsumq, g_gsumq);
    cudaGetSymbolAddress((void**)&accq, g_accq);
    cudaGetSymbolAddress((void**)&accda, g_accda);
    cudaGetSymbolAddress((void**)&aabq, g_aabq);
    cudaGetSymbolAddress((void**)&aabda, g_aabda);
    cudaGetSymbolAddress((void**)&mu, g_mu);
    cudaGetSymbolAddress((void**)&rstd, g_rstd);
    cudaGetSymbolAddress((void**)&pe, g_pe);
    cudaGetSymbolAddress((void**)&de, g_de);
    cudaGetSymbolAddress((void**)&dstat, g_dstat);
    cudaGetSymbolAddress((void**)&dg, g_deg);
    cudaGetSymbolAddress((void**)&coff, g_coff);
    cudaGetSymbolAddress((void**)&cursor, g_cursor);
    cudaGetSymbolAddress((void**)&srcs, g_srcs);
    cudaGetSymbolAddress((void**)&bsum, g_bsum);
    cudaGetSymbolAddress((void**)&dgq, g_degq);
    cudaGetSymbolAddress((void**)&coffq, g_coffq);
    cudaGetSymbolAddress((void**)&cursorq, g_cursorq);
    cudaGetSymbolAddress((void**)&srcsq, g_srcsq);
    cudaGetSymbolAddress((void**)&bsumq, g_bsumq);

    double* dstat1 = dstat + 512;
    float* mu1 = mu + 256;
    float* rstd1 = rstd + 256;

    cudaFuncSetAttribute(k_gemmW, cudaFuncAttributeMaxDynamicSharedMemorySize, SMEM_G1);
    cudaFuncSetAttribute(k_gemm<0, 1>, cudaFuncAttributeMaxDynamicSharedMemorySize, SMEM_G0);
    cudaFuncSetAttribute(k_gemm<2, 1>, cudaFuncAttributeMaxDynamicSharedMemorySize, SMEM_G0);

    const int YDA = cdiv(NDA, 128), YQ = cdiv(NQ, 128);
    const int E4A = EDA / 4, E4B = EQ / 4;

    // prep
    k_zero0<<<cdiv(NDA, 256), 256>>>(glq, gsumq, accq, accda, pe, de, dg, dgq, dstat);
    k_gapdots_b<<<NDA / 32 + NQ / 32, 1024>>>(h_da_0, h_da_last, gid_da, accda, h_q_0, h_q_last,
                                              gid_q, accq, gate1_W, gate1_b, gate2_W, gate2_b,
                                              Q_comb, gateq_W, gateq_b, eb, gsumq, NDA / 32);
    k_gap_pool<<<cdiv((long long)NQ * 32, 256), 256>>>(h_q_last, gid_q, eb, gsumq, glq, NQ);
    k_hist_b<<<cdiv(E4A + E4B, 256), 256>>>((const int4*)dst_da, dg, (const int4*)dst_q, dgq, E4A,
                                            E4B);
    // Qf FNN -> Qb
    k_gemm<0, 1><<<dim3(2, 1), 256, SMEM_G0>>>(glq, nullptr, Qf_W1, Qf_b1, nullptr, nullptr,
                                               nullptr, nullptr, t1, nullptr, dstat, nullptr, BB,
                                               0, 1, 128, 256);
    k_bnfin2<<<1, 512>>>(dstat, BB, mu, rstd, dstat1, 1, mu1, rstd1, 256);
    k_gemm<2, 1><<<dim3(2, 1), 256, SMEM_G0>>>(t1, nullptr, Qf_W2, Qf_b2, mu, rstd, nullptr,
                                               nullptr, t2, nullptr, dstat, nullptr, BB, 0, 1,
                                               256, 256);
    k_bnfin2<<<1, 512>>>(dstat, BB, mu, rstd, dstat1, 1, mu1, rstd1, 256);
    k_bnelu<<<cdiv(BB * 256, 256), 256>>>(t2, mu, rstd, Qb, (long long)BB * 256, 256);
    // CSR (+comb fused with scan2)
    int NBA = cdiv(NDA, 512), NBB = cdiv(NQ, 512);
    k_scan1_b<<<NBA + NBB, 256>>>(dg, coff, bsum, dgq, coffq, bsumq, NDA, NQ, NBA);
    k_scan2_comb<<<3, 256>>>(bsum, NBA, bsumq, NBB, accq, aabq, accda, aabda);
    k_scan3_b<<<cdiv(NDA + NQ, 256), 256>>>(coff, cursor, bsum, coffq, cursorq, bsumq, NDA, NQ);
    k_scatter_b<<<cdiv(E4A + E4B, 256), 256>>>((const int4*)src_da, (const int4*)dst_da, cursor,
                                               srcs, (const int4*)src_q, (const int4*)dst_q,
                                               cursorq, srcsq, E4A, E4B);

    // mega W_L GEMM (el/er fused; no feat stores)
    k_gemmW<<<dim3(1, 2 * (YDA + YQ)), 256, SMEM_G1>>>(
        h_da_last, h_q_last, h_da_0, h_q_0, aabda, aabq, gid_da, gid_q, W_L, b_L, Qb, ft, ftq, el,
        er, elq, erq, YDA, YQ);

    // batched node agg
    k_node_agg_b<<<cdiv((long long)(NDA + NQ) * 32, 256), 256>>>(
        srcs, coff, dg, el, er, ft, agg, ss, srcsq, coffq, dgq, elq, erq, ftq, aggq, sq2, NDA, NQ);
    // end FNN
    k_gemm<0, 1><<<dim3(2, YDA + YQ), 256, SMEM_G0>>>(agg, aggq, end_W1, end_b1, nullptr, nullptr,
                                                      nullptr, nullptr, y1, y1q, dstat, dstat1,
                                                      NDA, NQ, YDA, 128, 256);
    k_bnfin2<<<1, 512>>>(dstat, NDA, mu, rstd, dstat1, NQ, mu1, rstd1, 256);
    k_gemm<2, 1><<<dim3(1, YDA + YQ), 256, SMEM_G0>>>(y1, y1q, end_W2, end_b2, mu, rstd, mu1,
                                                      rstd1, y2, y2q, dstat, dstat1, NDA, NQ, YDA,
                                                      256, 128);
    k_bnfin2<<<1, 256>>>(dstat, NDA, mu, rstd, dstat1, NQ, mu1, rstd1, 128);
    k_final_b<<<cdiv((long long)(NDA + NQ) * HD, 256), 256>>>(
        h_da_last, y2, mu, rstd, out_da, h_q_last, y2q, mu1, rstd1, out_q, (long long)NDA * HD,
        (long long)NQ * HD);

    // loss
    k_pesum_b<<<128, 256>>>(PEid, nPE, pe, DEid, nDE, de, src_da, dst_da, el, er, ss);
    k_loss<<<1, 1>>>(pe, de, lenp, out_loss);
}